// round 15
// baseline (speedup 1.0000x reference)
#include <cuda_runtime.h>
#include <cstdint>

// Fixed problem: x [256,2048,7,7] fp32, x0 [256,49,1] fp32, out scalar fp32
#define BATCH   256
#define NQ      4                     // K-split partials per batch
#define NCTA    (BATCH * NQ)          // 1024
#define KQ      512                   // channels per CTA
#define KCH     32                    // channels per chunk
#define NCH     (KQ / KCH)            // 16 chunks
#define NDIM    49
#define CHF     (KCH * NDIM)          // 1568 floats per chunk
#define CHB     (CHF * 4)             // 6272 bytes (16B multiple)
#define STAGES  4
#define THREADS 128
#define EPSV    1e-12f

__device__ float g_partial[NCTA][NDIM * NDIM];
__device__ float g_penalty[BATCH];
__device__ int   g_cnt[BATCH];        // zero-init; reset by global last arriver
__device__ int   g_cnt_all;

static __device__ __forceinline__ uint32_t smem_u32(const void* p) {
    uint32_t a;
    asm("{ .reg .u64 t; cvta.to.shared.u64 t, %1; cvt.u32.u64 %0, t; }" : "=r"(a) : "l"(p));
    return a;
}

#define MBARRIER_INIT(addr, cnt) \
    asm volatile("mbarrier.init.shared.b64 [%0], %1;" :: "r"(addr), "r"(cnt) : "memory")
#define MBARRIER_ARRIVE(addr) \
    asm volatile("mbarrier.arrive.shared.b64 _, [%0];" :: "r"(addr) : "memory")
#define MBARRIER_EXPECT_TX(addr, bytes) \
    asm volatile("mbarrier.arrive.expect_tx.shared.b64 _, [%0], %1;" \
                 :: "r"(addr), "r"(bytes) : "memory")
#define TMA_BULK_1D(dst, src, bytes, mbar) \
    asm volatile("cp.async.bulk.shared::cta.global.mbarrier::complete_tx::bytes " \
                 "[%0], [%1], %2, [%3];" \
                 :: "r"(dst), "l"(src), "r"(bytes), "r"(mbar) : "memory")

#define MBARRIER_WAIT_PARITY(addr, par) do {                                        \
    uint32_t _m = (addr), _p = (par), _d;                                           \
    asm volatile("{\n\t.reg .pred p;\n\t"                                           \
        "mbarrier.try_wait.parity.acquire.cta.shared::cta.b64 p, [%1], %2;\n\t"     \
        "selp.b32 %0, 1, 0, p;\n\t}"                                                \
        : "=r"(_d) : "r"(_m), "r"(_p) : "memory");                                  \
    if (!_d) {                                                                      \
        asm volatile("{\n\t.reg .pred P1;\n\t"                                      \
            "WL_%=:\n\t"                                                            \
            "mbarrier.try_wait.parity.acquire.cta.shared::cta.b64 P1, [%0], %1, 0x989680;\n\t" \
            "@P1 bra.uni WD_%=;\n\t"                                                \
            "bra.uni WL_%=;\n\t"                                                    \
            "WD_%=:\n\t}"                                                           \
            :: "r"(_m), "r"(_p) : "memory");                                        \
    }                                                                               \
} while (0)

// m16n8k8 tf32 mma on raw fp32 bits (HW truncates to tf32). sm_80 PTX.
static __device__ __forceinline__ void mma8(float* c,
    uint32_t a0, uint32_t a1, uint32_t a2, uint32_t a3,
    uint32_t b0, uint32_t b1)
{
    asm("mma.sync.aligned.m16n8k8.row.col.f32.tf32.tf32.f32 "
        "{%0,%1,%2,%3}, {%4,%5,%6,%7}, {%8,%9}, {%0,%1,%2,%3};"
        : "+f"(c[0]), "+f"(c[1]), "+f"(c[2]), "+f"(c[3])
        : "r"(a0), "r"(a1), "r"(a2), "r"(a3), "r"(b0), "r"(b1));
}

static __device__ __forceinline__ float warpsum(float v) {
    v += __shfl_xor_sync(0xffffffffu, v, 16);
    v += __shfl_xor_sync(0xffffffffu, v, 8);
    v += __shfl_xor_sync(0xffffffffu, v, 4);
    v += __shfl_xor_sync(0xffffffffu, v, 2);
    v += __shfl_xor_sync(0xffffffffu, v, 1);
    return v;
}

// matvec row dot with 4 accumulators (breaks the 49-deep FMA chain)
static __device__ __forceinline__ float dot49(const float* __restrict__ row,
                                              const float* __restrict__ v) {
    float a0 = 0.f, a1 = 0.f, a2 = 0.f, a3 = 0.f;
#pragma unroll
    for (int m = 0; m < 48; m += 4) {
        a0 = fmaf(row[m + 0], v[m + 0], a0);
        a1 = fmaf(row[m + 1], v[m + 1], a1);
        a2 = fmaf(row[m + 2], v[m + 2], a2);
        a3 = fmaf(row[m + 3], v[m + 3], a3);
    }
    return (a0 + a1) + (a2 + a3) + row[48] * v[48];
}

__global__ void __launch_bounds__(THREADS, 8)
ofp_fused(const float* __restrict__ x, const float* __restrict__ x0,
          float* __restrict__ out)
{
    __shared__ __align__(16) float sbuf[STAGES * CHF + 16];  // +16 zero pad for overreads
    __shared__ __align__(8) unsigned long long fullb[STAGES];
    __shared__ __align__(8) unsigned long long emptyb[STAGES];
    __shared__ float sx[64];
    __shared__ int scomm;
    float* sA = sbuf;                         // 2401 floats; stage buffers dead by PI time

    const int t    = threadIdx.x;
    const int lane = t & 31, wid = t >> 5;
    const int l4   = lane & 3, ld4 = lane >> 2;
    const int cta  = blockIdx.x;
    const int b    = cta >> 2, q = cta & 3;
    const int qm   = wid >> 1, qn = wid & 1;  // warp's 32x32 quadrant
    const int m0   = qm * 32 + ld4;
    const int n0f  = qn * 32 + ld4;

    const float* __restrict__ xq =
        x + (size_t)b * (2048 * NDIM) + (size_t)q * (KQ * NDIM);

    const uint32_t sbase = smem_u32(sbuf);
    const uint32_t fbase = smem_u32(fullb);
    const uint32_t ebase = smem_u32(emptyb);

    if (t < STAGES) {
        MBARRIER_INIT(fbase + 8u * t, 1u);    // completes via expect_tx + TMA tx
        MBARRIER_INIT(ebase + 8u * t, 4u);    // one arrive per warp
    }
    if (t < 16) sbuf[STAGES * CHF + t] = 0.0f;
    __syncthreads();

    float acc[2][4][4];
#pragma unroll
    for (int mt = 0; mt < 2; mt++)
#pragma unroll
        for (int nt = 0; nt < 4; nt++)
#pragma unroll
            for (int ci = 0; ci < 4; ci++) acc[mt][nt][ci] = 0.0f;

    // prologue: issue chunks 0..2
    if (t == 0) {
#pragma unroll
        for (int s = 0; s < STAGES - 1; s++) {
            MBARRIER_EXPECT_TX(fbase + 8u * s, (uint32_t)CHB);
            TMA_BULK_1D(sbase + (uint32_t)(s * CHB), xq + (size_t)s * CHF,
                        (uint32_t)CHB, fbase + 8u * s);
        }
    }

    // main loop: barrier-free mbarrier pipeline (R13-proven)
    for (int ch = 0; ch < NCH; ch++) {
        const uint32_t slot = (uint32_t)(ch & (STAGES - 1));

        if (t == 0 && ch + STAGES - 1 < NCH) {
            const int s = ch + STAGES - 1;
            const uint32_t sl = (uint32_t)(s & (STAGES - 1));
            if (s >= STAGES)
                MBARRIER_WAIT_PARITY(ebase + 8u * sl, (uint32_t)(((s - STAGES) >> 2) & 1));
            MBARRIER_EXPECT_TX(fbase + 8u * sl, (uint32_t)CHB);
            TMA_BULK_1D(sbase + sl * (uint32_t)CHB, xq + (size_t)s * CHF,
                        (uint32_t)CHB, fbase + 8u * sl);
        }

        MBARRIER_WAIT_PARITY(fbase + 8u * slot, (uint32_t)((ch >> 2) & 1));

        const float* bc = sbuf + slot * CHF;
#pragma unroll
        for (int kb = 0; kb < 4; kb++) {
            const float* lo = bc + (kb * 8 + l4) * NDIM;
            const float* hi = lo + 4 * NDIM;
            uint32_t b0[4], b1[4];
#pragma unroll
            for (int nt = 0; nt < 4; nt++) {
                b0[nt] = __float_as_uint(lo[n0f + nt * 8]);
                b1[nt] = __float_as_uint(hi[n0f + nt * 8]);
            }
#pragma unroll
            for (int mt = 0; mt < 2; mt++) {
                const uint32_t a0 = __float_as_uint(lo[m0 + mt * 16]);
                const uint32_t a1 = __float_as_uint(lo[m0 + mt * 16 + 8]);
                const uint32_t a2 = __float_as_uint(hi[m0 + mt * 16]);
                const uint32_t a3 = __float_as_uint(hi[m0 + mt * 16 + 8]);
#pragma unroll
                for (int nt = 0; nt < 4; nt++)
                    mma8(acc[mt][nt], a0, a1, a2, a3, b0[nt], b1[nt]);
            }
        }
        __syncwarp();
        if (lane == 0) MBARRIER_ARRIVE(ebase + 8u * slot);
    }

    // write 49x49 partial Gram
    {
        float* __restrict__ gp = g_partial[cta];
#pragma unroll
        for (int mt = 0; mt < 2; mt++)
#pragma unroll
            for (int nt = 0; nt < 4; nt++) {
                const int rr = qm * 32 + mt * 16 + ld4;
                const int cc = qn * 32 + nt * 8 + 2 * l4;
                const float* a = acc[mt][nt];
                if (rr < NDIM) {
                    if (cc < NDIM)     gp[rr * NDIM + cc]     = a[0];
                    if (cc + 1 < NDIM) gp[rr * NDIM + cc + 1] = a[1];
                }
                if (rr + 8 < NDIM) {
                    if (cc < NDIM)     gp[(rr + 8) * NDIM + cc]     = a[2];
                    if (cc + 1 < NDIM) gp[(rr + 8) * NDIM + cc + 1] = a[3];
                }
            }
    }
    __syncthreads();                          // all partial stores issued
    __threadfence();
    if (t == 0) scomm = atomicAdd(&g_cnt[b], 1);
    __syncthreads();
    if (scomm != NQ - 1) return;              // not the last partial of this batch

    // ============ last arriver for batch b: gather + PI (overlaps other batches' Gram) ============
    __threadfence();
    {
        const float* __restrict__ p0 = g_partial[(b << 2) + 0];
        const float* __restrict__ p1 = g_partial[(b << 2) + 1];
        const float* __restrict__ p2 = g_partial[(b << 2) + 2];
        const float* __restrict__ p3 = g_partial[(b << 2) + 3];
        for (int i = t; i < NDIM * NDIM; i += THREADS)
            sA[i] = (__ldcg(p0 + i) + __ldcg(p1 + i)) +
                    (__ldcg(p2 + i) + __ldcg(p3 + i));
    }
    if (t < NDIM) sx[t] = x0[b * NDIM + t];
    if (t >= NDIM && t < 64) sx[t] = 0.0f;
    __syncthreads();
    if (wid != 0) return;                     // PI on warp 0 only

    const bool has2 = (lane < NDIM - 32);
    float rA0[NDIM], rA1[NDIM];
#pragma unroll
    for (int m = 0; m < NDIM; m++) {
        rA0[m] = sA[lane * NDIM + m];
        rA1[m] = has2 ? sA[(lane + 32) * NDIM + m] : 0.0f;
    }

    // PI-1: largest eigenvalue of ATA
    for (int it = 0; it < 9; it++) {
        float y0 = dot49(rA0, sx);
        float y1 = has2 ? dot49(rA1, sx) : 0.0f;
        const float n2  = warpsum(y0 * y0 + y1 * y1);
        const float inv = 1.0f / fmaxf(sqrtf(n2), EPSV);
        sx[lane] = y0 * inv;
        if (has2) sx[lane + 32] = y1 * inv;
        __syncwarp();
    }
    float largest;
    {
        const float y0 = dot49(rA0, sx);
        const float y1 = has2 ? dot49(rA1, sx) : 0.0f;
        const float x0v = sx[lane];
        const float x1v = has2 ? sx[lane + 32] : 0.0f;
        const float num = warpsum(y0 * x0v + y1 * x1v);
        const float den = warpsum(x0v * x0v + x1v * x1v);
        largest = num / den;
    }

    // PI-2 on (ATA - largest*I), warm-started from x1
    for (int it = 0; it < 9; it++) {
        float z0 = dot49(rA0, sx) - largest * sx[lane];
        float z1 = has2 ? (dot49(rA1, sx) - largest * sx[lane + 32]) : 0.0f;
        const float n2  = warpsum(z0 * z0 + z1 * z1);
        const float inv = 1.0f / fmaxf(sqrtf(n2), EPSV);
        sx[lane] = z0 * inv;
        if (has2) sx[lane + 32] = z1 * inv;
        __syncwarp();
    }
    {
        const float u0 = sx[lane];
        const float u1 = has2 ? sx[lane + 32] : 0.0f;
        const float z0 = dot49(rA0, sx) - largest * u0;
        const float z1 = has2 ? (dot49(rA1, sx) - largest * u1) : 0.0f;
        const float num2 = warpsum(z0 * u0 + z1 * u1);
        const float den2 = warpsum(u0 * u0 + u1 * u1);
        const float smallest = (num2 / den2) + largest;
        if (lane == 0) {
            const float r = largest / smallest - 1.0f;
            g_penalty[b] = r * r;             // BETA = 1
        }
    }

    // ============ global last arriver: deterministic finalize + counter reset ============
    __threadfence();
    int old = 0;
    if (lane == 0) old = atomicAdd(&g_cnt_all, 1);
    old = __shfl_sync(0xffffffffu, old, 0);
    if (old != BATCH - 1) return;

    __threadfence();
    float s = 0.0f;
#pragma unroll
    for (int k = 0; k < BATCH / 32; k++)      // fixed order -> deterministic
        s += __ldcg(&g_penalty[lane + 32 * k]);
    s = warpsum(s);
#pragma unroll
    for (int k = 0; k < BATCH / 32; k++)      // reset per-batch counters for replay
        g_cnt[lane + 32 * k] = 0;
    if (lane == 0) {
        out[0] = s * (1.0f / (float)BATCH);
        g_cnt_all = 0;
    }
}

extern "C" void kernel_launch(void* const* d_in, const int* in_sizes, int n_in,
                              void* d_out, int out_size) {
    const float* x  = (const float*)d_in[0];   // [256, 2048, 7, 7]
    const float* x0 = (const float*)d_in[1];   // [256, 49, 1]
    float* out = (float*)d_out;

    ofp_fused<<<NCTA, THREADS>>>(x, x0, out);
}

// round 16
// speedup vs baseline: 1.9901x; 1.9901x over previous
#include <cuda_runtime.h>
#include <cstdint>

// Fixed problem: x [256,2048,7,7] fp32, x0 [256,49,1] fp32, out scalar fp32
#define BATCH   256
#define NQ      4                     // K-split partials per batch
#define NCTA    (BATCH * NQ)          // 1024
#define KQ      512                   // channels per CTA
#define KCH     32                    // channels per chunk
#define NCH     (KQ / KCH)            // 16 chunks
#define NDIM    49
#define CHF     (KCH * NDIM)          // 1568 floats per chunk
#define CHB     (CHF * 4)             // 6272 bytes (16B multiple)
#define STAGES  4
#define THREADS 128
#define PADN    2404                  // 49*49=2401 padded to /4 (row = 9616 B, 16B-aligned)
#define PADN4   (PADN / 4)            // 601 float4 per partial
#define EPSV    1e-12f

__device__ __align__(16) float g_partial[NCTA][PADN];
__device__ float g_penalty[BATCH];
__device__ int   g_cnt_all;           // zero-init; reset by global last arriver

static __device__ __forceinline__ uint32_t smem_u32(const void* p) {
    uint32_t a;
    asm("{ .reg .u64 t; cvta.to.shared.u64 t, %1; cvt.u32.u64 %0, t; }" : "=r"(a) : "l"(p));
    return a;
}

#define MBARRIER_INIT(addr, cnt) \
    asm volatile("mbarrier.init.shared.b64 [%0], %1;" :: "r"(addr), "r"(cnt) : "memory")
#define MBARRIER_ARRIVE(addr) \
    asm volatile("mbarrier.arrive.shared.b64 _, [%0];" :: "r"(addr) : "memory")
#define MBARRIER_EXPECT_TX(addr, bytes) \
    asm volatile("mbarrier.arrive.expect_tx.shared.b64 _, [%0], %1;" \
                 :: "r"(addr), "r"(bytes) : "memory")
#define TMA_BULK_1D(dst, src, bytes, mbar) \
    asm volatile("cp.async.bulk.shared::cta.global.mbarrier::complete_tx::bytes " \
                 "[%0], [%1], %2, [%3];" \
                 :: "r"(dst), "l"(src), "r"(bytes), "r"(mbar) : "memory")

#define MBARRIER_WAIT_PARITY(addr, par) do {                                        \
    uint32_t _m = (addr), _p = (par), _d;                                           \
    asm volatile("{\n\t.reg .pred p;\n\t"                                           \
        "mbarrier.try_wait.parity.acquire.cta.shared::cta.b64 p, [%1], %2;\n\t"     \
        "selp.b32 %0, 1, 0, p;\n\t}"                                                \
        : "=r"(_d) : "r"(_m), "r"(_p) : "memory");                                  \
    if (!_d) {                                                                      \
        asm volatile("{\n\t.reg .pred P1;\n\t"                                      \
            "WL_%=:\n\t"                                                            \
            "mbarrier.try_wait.parity.acquire.cta.shared::cta.b64 P1, [%0], %1, 0x989680;\n\t" \
            "@P1 bra.uni WD_%=;\n\t"                                                \
            "bra.uni WL_%=;\n\t"                                                    \
            "WD_%=:\n\t}"                                                           \
            :: "r"(_m), "r"(_p) : "memory");                                        \
    }                                                                               \
} while (0)

// m16n8k8 tf32 mma on raw fp32 bits (HW truncates to tf32). sm_80 PTX.
static __device__ __forceinline__ void mma8(float* c,
    uint32_t a0, uint32_t a1, uint32_t a2, uint32_t a3,
    uint32_t b0, uint32_t b1)
{
    asm("mma.sync.aligned.m16n8k8.row.col.f32.tf32.tf32.f32 "
        "{%0,%1,%2,%3}, {%4,%5,%6,%7}, {%8,%9}, {%0,%1,%2,%3};"
        : "+f"(c[0]), "+f"(c[1]), "+f"(c[2]), "+f"(c[3])
        : "r"(a0), "r"(a1), "r"(a2), "r"(a3), "r"(b0), "r"(b1));
}

static __device__ __forceinline__ float warpsum(float v) {
    v += __shfl_xor_sync(0xffffffffu, v, 16);
    v += __shfl_xor_sync(0xffffffffu, v, 8);
    v += __shfl_xor_sync(0xffffffffu, v, 4);
    v += __shfl_xor_sync(0xffffffffu, v, 2);
    v += __shfl_xor_sync(0xffffffffu, v, 1);
    return v;
}

// matvec row dot with 4 accumulators (breaks the 49-deep FMA chain)
static __device__ __forceinline__ float dot49(const float* __restrict__ row,
                                              const float* __restrict__ v) {
    float a0 = 0.f, a1 = 0.f, a2 = 0.f, a3 = 0.f;
#pragma unroll
    for (int m = 0; m < 48; m += 4) {
        a0 = fmaf(row[m + 0], v[m + 0], a0);
        a1 = fmaf(row[m + 1], v[m + 1], a1);
        a2 = fmaf(row[m + 2], v[m + 2], a2);
        a3 = fmaf(row[m + 3], v[m + 3], a3);
    }
    return (a0 + a1) + (a2 + a3) + row[48] * v[48];
}

// ============================ kernel 1: Gram (R13-proven, stride PADN) ============================
__global__ void __launch_bounds__(THREADS, 8)
ofp_gram(const float* __restrict__ x)
{
    __shared__ __align__(16) float sbuf[STAGES * CHF + 16];  // +16 zero pad for overreads
    __shared__ __align__(8) unsigned long long fullb[STAGES];
    __shared__ __align__(8) unsigned long long emptyb[STAGES];

    const int t    = threadIdx.x;
    const int lane = t & 31, wid = t >> 5;
    const int l4   = lane & 3, ld4 = lane >> 2;
    const int cta  = blockIdx.x;
    const int b    = cta >> 2, q = cta & 3;
    const int qm   = wid >> 1, qn = wid & 1;  // warp's 32x32 quadrant
    const int m0   = qm * 32 + ld4;
    const int n0f  = qn * 32 + ld4;

    const float* __restrict__ xq =
        x + (size_t)b * (2048 * NDIM) + (size_t)q * (KQ * NDIM);

    const uint32_t sbase = smem_u32(sbuf);
    const uint32_t fbase = smem_u32(fullb);
    const uint32_t ebase = smem_u32(emptyb);

    if (t < STAGES) {
        MBARRIER_INIT(fbase + 8u * t, 1u);    // completes via expect_tx + TMA tx
        MBARRIER_INIT(ebase + 8u * t, 4u);    // one arrive per warp
    }
    if (t < 16) sbuf[STAGES * CHF + t] = 0.0f;
    __syncthreads();                          // the only block barrier

    float acc[2][4][4];
#pragma unroll
    for (int mt = 0; mt < 2; mt++)
#pragma unroll
        for (int nt = 0; nt < 4; nt++)
#pragma unroll
            for (int ci = 0; ci < 4; ci++) acc[mt][nt][ci] = 0.0f;

    if (t == 0) {
#pragma unroll
        for (int s = 0; s < STAGES - 1; s++) {
            MBARRIER_EXPECT_TX(fbase + 8u * s, (uint32_t)CHB);
            TMA_BULK_1D(sbase + (uint32_t)(s * CHB), xq + (size_t)s * CHF,
                        (uint32_t)CHB, fbase + 8u * s);
        }
    }

    for (int ch = 0; ch < NCH; ch++) {
        const uint32_t slot = (uint32_t)(ch & (STAGES - 1));

        if (t == 0 && ch + STAGES - 1 < NCH) {
            const int s = ch + STAGES - 1;
            const uint32_t sl = (uint32_t)(s & (STAGES - 1));
            if (s >= STAGES)
                MBARRIER_WAIT_PARITY(ebase + 8u * sl, (uint32_t)(((s - STAGES) >> 2) & 1));
            MBARRIER_EXPECT_TX(fbase + 8u * sl, (uint32_t)CHB);
            TMA_BULK_1D(sbase + sl * (uint32_t)CHB, xq + (size_t)s * CHF,
                        (uint32_t)CHB, fbase + 8u * sl);
        }

        MBARRIER_WAIT_PARITY(fbase + 8u * slot, (uint32_t)((ch >> 2) & 1));

        const float* bc = sbuf + slot * CHF;
#pragma unroll
        for (int kb = 0; kb < 4; kb++) {
            const float* lo = bc + (kb * 8 + l4) * NDIM;
            const float* hi = lo + 4 * NDIM;
            uint32_t b0[4], b1[4];
#pragma unroll
            for (int nt = 0; nt < 4; nt++) {
                b0[nt] = __float_as_uint(lo[n0f + nt * 8]);
                b1[nt] = __float_as_uint(hi[n0f + nt * 8]);
            }
#pragma unroll
            for (int mt = 0; mt < 2; mt++) {
                const uint32_t a0 = __float_as_uint(lo[m0 + mt * 16]);
                const uint32_t a1 = __float_as_uint(lo[m0 + mt * 16 + 8]);
                const uint32_t a2 = __float_as_uint(hi[m0 + mt * 16]);
                const uint32_t a3 = __float_as_uint(hi[m0 + mt * 16 + 8]);
#pragma unroll
                for (int nt = 0; nt < 4; nt++)
                    mma8(acc[mt][nt], a0, a1, a2, a3, b0[nt], b1[nt]);
            }
        }
        __syncwarp();
        if (lane == 0) MBARRIER_ARRIVE(ebase + 8u * slot);
    }

    float* __restrict__ gp = g_partial[cta];
#pragma unroll
    for (int mt = 0; mt < 2; mt++)
#pragma unroll
        for (int nt = 0; nt < 4; nt++) {
            const int rr = qm * 32 + mt * 16 + ld4;
            const int cc = qn * 32 + nt * 8 + 2 * l4;
            const float* a = acc[mt][nt];
            if (rr < NDIM) {
                if (cc < NDIM)     gp[rr * NDIM + cc]     = a[0];
                if (cc + 1 < NDIM) gp[rr * NDIM + cc + 1] = a[1];
            }
            if (rr + 8 < NDIM) {
                if (cc < NDIM)     gp[(rr + 8) * NDIM + cc]     = a[2];
                if (cc + 1 < NDIM) gp[(rr + 8) * NDIM + cc + 1] = a[3];
            }
        }
}

// ============================ kernel 2: PI x2 per CTA + fused finalize ============================
__global__ void ofp_pi2(const float* __restrict__ x0, float* __restrict__ out)
{
    __shared__ __align__(16) float sA[2][PADN];
    __shared__ float sx[2][64];

    const int t    = threadIdx.x;
    const int half = t >> 7;                    // 0 or 1: which batch of the pair
    const int th   = t & 127;                   // thread index within half
    const int lane = th & 31;
    const int b    = (blockIdx.x << 1) + half;

    // float4 gather of the 4 partials for this half's batch (128 threads each)
    {
        const float4* __restrict__ p0 = (const float4*)g_partial[(b << 2) + 0];
        const float4* __restrict__ p1 = (const float4*)g_partial[(b << 2) + 1];
        const float4* __restrict__ p2 = (const float4*)g_partial[(b << 2) + 2];
        const float4* __restrict__ p3 = (const float4*)g_partial[(b << 2) + 3];
        float4* __restrict__ dst = (float4*)sA[half];
#pragma unroll 5
        for (int i = th; i < PADN4; i += 128) {
            const float4 v0 = p0[i], v1 = p1[i], v2 = p2[i], v3 = p3[i];
            float4 r;
            r.x = (v0.x + v1.x) + (v2.x + v3.x);
            r.y = (v0.y + v1.y) + (v2.y + v3.y);
            r.z = (v0.z + v1.z) + (v2.z + v3.z);
            r.w = (v0.w + v1.w) + (v2.w + v3.w);
            dst[i] = r;
        }
    }
    if (th < NDIM) sx[half][th] = x0[b * NDIM + th];
    if (th >= NDIM && th < 64) sx[half][th] = 0.0f;
    __syncthreads();

    if ((th >> 5) != 0) return;                 // PI on warp 0 of each half

    const float* __restrict__ A = sA[half];
    float* __restrict__ xv = sx[half];

    const bool has2 = (lane < NDIM - 32);
    float rA0[NDIM], rA1[NDIM];
#pragma unroll
    for (int m = 0; m < NDIM; m++) {
        rA0[m] = A[lane * NDIM + m];
        rA1[m] = has2 ? A[(lane + 32) * NDIM + m] : 0.0f;
    }

    // PI-1: largest eigenvalue of ATA
    for (int it = 0; it < 9; it++) {
        float y0 = dot49(rA0, xv);
        float y1 = has2 ? dot49(rA1, xv) : 0.0f;
        const float n2  = warpsum(y0 * y0 + y1 * y1);
        const float inv = 1.0f / fmaxf(sqrtf(n2), EPSV);
        xv[lane] = y0 * inv;
        if (has2) xv[lane + 32] = y1 * inv;
        __syncwarp();
    }
    float largest;
    {
        const float y0 = dot49(rA0, xv);
        const float y1 = has2 ? dot49(rA1, xv) : 0.0f;
        const float u0 = xv[lane];
        const float u1 = has2 ? xv[lane + 32] : 0.0f;
        const float num = warpsum(y0 * u0 + y1 * u1);
        const float den = warpsum(u0 * u0 + u1 * u1);
        largest = num / den;
    }

    // PI-2 on (ATA - largest*I), warm-started from x1
    for (int it = 0; it < 9; it++) {
        float z0 = dot49(rA0, xv) - largest * xv[lane];
        float z1 = has2 ? (dot49(rA1, xv) - largest * xv[lane + 32]) : 0.0f;
        const float n2  = warpsum(z0 * z0 + z1 * z1);
        const float inv = 1.0f / fmaxf(sqrtf(n2), EPSV);
        xv[lane] = z0 * inv;
        if (has2) xv[lane + 32] = z1 * inv;
        __syncwarp();
    }
    {
        const float u0 = xv[lane];
        const float u1 = has2 ? xv[lane + 32] : 0.0f;
        const float z0 = dot49(rA0, xv) - largest * u0;
        const float z1 = has2 ? (dot49(rA1, xv) - largest * u1) : 0.0f;
        const float num2 = warpsum(z0 * u0 + z1 * u1);
        const float den2 = warpsum(u0 * u0 + u1 * u1);
        const float smallest = (num2 / den2) + largest;
        if (lane == 0) {
            const float r = largest / smallest - 1.0f;
            g_penalty[b] = r * r;               // BETA = 1
        }
    }

    // -------- fused finalize: global last-arriver warp sums all penalties --------
    __threadfence();
    int old = 0;
    if (lane == 0) old = atomicAdd(&g_cnt_all, 1);
    old = __shfl_sync(0xffffffffu, old, 0);
    if (old != BATCH - 1) return;

    __threadfence();
    float s = 0.0f;
#pragma unroll
    for (int k = 0; k < BATCH / 32; k++)        // fixed order -> deterministic
        s += __ldcg(&g_penalty[lane + 32 * k]);
    s = warpsum(s);
    if (lane == 0) {
        out[0] = s * (1.0f / (float)BATCH);
        g_cnt_all = 0;                          // reset for graph replay
    }
}

extern "C" void kernel_launch(void* const* d_in, const int* in_sizes, int n_in,
                              void* d_out, int out_size) {
    const float* x  = (const float*)d_in[0];   // [256, 2048, 7, 7]
    const float* x0 = (const float*)d_in[1];   // [256, 49, 1]
    float* out = (float*)d_out;

    ofp_gram<<<NCTA, THREADS>>>(x);
    ofp_pi2<<<BATCH / 2, 256>>>(x0, out);
}